// round 13
// baseline (speedup 1.0000x reference)
#include <cuda_runtime.h>
#include <cuda_bf16.h>
#include <math.h>
#include <stdint.h>

#define M_TOK 16384
#define D_DIM 2048
#define E_EXP 64
#define H_DIM 1024

// ---- scratch (static __device__ arrays: allocation-free) ----
__device__ float g_mu[M_TOK];
__device__ float g_rs[M_TOK];
__device__ float g_z[M_TOK];
__device__ float g_logits[M_TOK * E_EXP];                 // 4 MB
__device__ __nv_bfloat16 g_xb[(size_t)M_TOK * D_DIM];     // 64 MB
__device__ __nv_bfloat16 g_Wb[(size_t)H_DIM * D_DIM];     // 4 MB (gamma*W1 bf16)
__device__ float g_Wgs[(size_t)E_EXP * D_DIM * 2];        // 1 MB tf32 (hi,lo) pairs of Wg
__device__ float g_s[H_DIM];
__device__ float g_t[H_DIM];

// =================== PTX helpers (family-generic only) ===================
__device__ __forceinline__ uint32_t smem_u32(const void* p) {
    return (uint32_t)__cvta_generic_to_shared(p);
}
__device__ __forceinline__ void cp16(uint32_t dst, const void* src) {
    asm volatile("cp.async.cg.shared.global [%0], [%1], 16;" :: "r"(dst), "l"(src));
}
__device__ __forceinline__ void cp_commit() { asm volatile("cp.async.commit_group;"); }
__device__ __forceinline__ void cp_wait2()  { asm volatile("cp.async.wait_group 2;"); }
__device__ __forceinline__ void ldm4(uint32_t* r, uint32_t addr) {
    asm volatile("ldmatrix.sync.aligned.m8n8.x4.shared.b16 {%0,%1,%2,%3}, [%4];"
                 : "=r"(r[0]), "=r"(r[1]), "=r"(r[2]), "=r"(r[3]) : "r"(addr));
}
__device__ __forceinline__ void mma16816(float* c, const uint32_t* a, uint32_t b0, uint32_t b1) {
    asm volatile("mma.sync.aligned.m16n8k16.row.col.f32.bf16.bf16.f32 "
                 "{%0,%1,%2,%3}, {%4,%5,%6,%7}, {%8,%9}, {%0,%1,%2,%3};"
                 : "+f"(c[0]), "+f"(c[1]), "+f"(c[2]), "+f"(c[3])
                 : "r"(a[0]), "r"(a[1]), "r"(a[2]), "r"(a[3]), "r"(b0), "r"(b1));
}
__device__ __forceinline__ void mma1688t(float* c, uint32_t a0, uint32_t a1, uint32_t a2,
                                         uint32_t a3, uint32_t b0, uint32_t b1) {
    asm volatile("mma.sync.aligned.m16n8k8.row.col.f32.tf32.tf32.f32 "
                 "{%0,%1,%2,%3}, {%4,%5,%6,%7}, {%8,%9}, {%0,%1,%2,%3};"
                 : "+f"(c[0]), "+f"(c[1]), "+f"(c[2]), "+f"(c[3])
                 : "r"(a0), "r"(a1), "r"(a2), "r"(a3), "r"(b0), "r"(b1));
}
__device__ __forceinline__ uint2 lds64(uint32_t a) {
    uint2 r;
    asm volatile("ld.shared.v2.b32 {%0,%1}, [%2];" : "=r"(r.x), "=r"(r.y) : "r"(a));
    return r;
}
__device__ __forceinline__ float lds32(uint32_t a) {
    float r;
    asm volatile("ld.shared.b32 %0, [%1];" : "=f"(r) : "r"(a));
    return r;
}
// 3xTF32 split: BOTH halves go through cvt.rna.tf32 so the MMA input
// registers hold exact tf32 values (the tensor core adds no further error).
// R9 lesson: a bit-masked hi + raw-fp32 lo gets truncated inside the MMA and
// the biased residuals flipped top-k indices (rel_err 2.3e-3). Do not
// "optimize" this back to a mask split.
__device__ __forceinline__ uint2 tf32split(float v) {
    uint32_t hi, lo;
    asm("cvt.rna.tf32.f32 %0, %1;" : "=r"(hi) : "f"(v));
    float r = v - __uint_as_float(hi);
    asm("cvt.rna.tf32.f32 %0, %1;" : "=r"(lo) : "f"(r));
    return make_uint2(hi, lo);
}

// ---------------- init: zero z and importance/load region of d_out --------
__global__ void k_init(float* __restrict__ d_impload) {
    int i = blockIdx.x * blockDim.x + threadIdx.x;
    if (i < M_TOK) g_z[i] = 0.0f;
    if (i < 128)   d_impload[i] = 0.0f;
}

// ---------------- per-token LN stats + bf16 convert (x read once) ---------
__global__ void k_stats_cvt(const float* __restrict__ x) {
    int t = blockIdx.x;
    const float4* xr = (const float4*)(x + (size_t)t * D_DIM);
    __nv_bfloat162* xb = (__nv_bfloat162*)(g_xb + (size_t)t * D_DIM);
    float s = 0.f, ss = 0.f;
    for (int i = threadIdx.x; i < D_DIM / 4; i += blockDim.x) {
        float4 v = xr[i];
        s  += v.x + v.y + v.z + v.w;
        ss += v.x * v.x + v.y * v.y + v.z * v.z + v.w * v.w;
        xb[2 * i + 0] = __floats2bfloat162_rn(v.x, v.y);
        xb[2 * i + 1] = __floats2bfloat162_rn(v.z, v.w);
    }
    #pragma unroll
    for (int o = 16; o; o >>= 1) {
        s  += __shfl_xor_sync(0xffffffffu, s,  o);
        ss += __shfl_xor_sync(0xffffffffu, ss, o);
    }
    __shared__ float red[2][8];
    int w = threadIdx.x >> 5;
    if ((threadIdx.x & 31) == 0) { red[0][w] = s; red[1][w] = ss; }
    __syncthreads();
    if (threadIdx.x == 0) {
        float S = 0.f, SS = 0.f;
        for (int i = 0; i < (int)(blockDim.x >> 5); i++) { S += red[0][i]; SS += red[1][i]; }
        float mu  = S / (float)D_DIM;
        float var = SS / (float)D_DIM - mu * mu;
        g_mu[t] = mu;
        g_rs[t] = rsqrtf(var + 1e-5f);
    }
}

// ---------------- prep: Wb = bf16(gamma*W1), s_j, t_j ; Wg tf32 split -----
__global__ void k_prep(const float* __restrict__ gamma, const float* __restrict__ beta,
                       const float* __restrict__ W1, const float* __restrict__ Wg) {
    int n = blockIdx.x;
    if (n >= H_DIM) {
        int e = n - H_DIM;
        const float* src = Wg + (size_t)e * D_DIM;
        float2* dst = (float2*)(g_Wgs + (size_t)e * D_DIM * 2);
        for (int i = threadIdx.x; i < D_DIM; i += blockDim.x) {
            uint2 p = tf32split(src[i]);
            dst[i] = make_float2(__uint_as_float(p.x), __uint_as_float(p.y));
        }
        return;
    }
    int j = n;
    const float* w1r = W1 + (size_t)j * D_DIM;
    __nv_bfloat16* dst = g_Wb + (size_t)j * D_DIM;
    float sj = 0.f, tj = 0.f;
    for (int i = threadIdx.x; i < D_DIM; i += blockDim.x) {
        float g = gamma[i], w = w1r[i];
        float gw = g * w;
        dst[i] = __float2bfloat16_rn(gw);
        sj += gw;
        tj += beta[i] * w;
    }
    #pragma unroll
    for (int o = 16; o; o >>= 1) {
        sj += __shfl_xor_sync(0xffffffffu, sj, o);
        tj += __shfl_xor_sync(0xffffffffu, tj, o);
    }
    __shared__ float red[2][8];
    int w = threadIdx.x >> 5;
    if ((threadIdx.x & 31) == 0) { red[0][w] = sj; red[1][w] = tj; }
    __syncthreads();
    if (threadIdx.x == 0) {
        float S = 0.f, T = 0.f;
        for (int i = 0; i < (int)(blockDim.x >> 5); i++) { S += red[0][i]; T += red[1][i]; }
        g_s[j] = S; g_t[j] = T;
    }
}

// ---------------- logits: 3xTF32 tensor GEMM, BM=64 x N=64, BK=32 ---------
// 512 threads = 16 warps: warp_m = wid&3 (16 rows), warp_n = wid>>2 (16 cols).
// 4-stage cp.async, depth-3 prefetch. A raw fp32 (stride 144B), cvt.rna
// tf32-split at fragment load. B pre-split (hi,lo) pairs (stride 288B).
#define LGA_STRIDE 144
#define LGB_STRIDE 288
#define LGA_TILE (64 * LGA_STRIDE)            // 9216
#define LGB_TILE (64 * LGB_STRIDE)            // 18432
#define LG_STAGE (LGA_TILE + LGB_TILE)        // 27648
#define LG_SMEM  (4 * LG_STAGE)               // 110592

__global__ __launch_bounds__(512, 2)
void k_logits(const float* __restrict__ x) {
    extern __shared__ __align__(16) char lsm[];
    const int tid = threadIdx.x;
    const int wid = tid >> 5, lane = tid & 31;
    const int warp_m = wid & 3, warp_n = wid >> 2;    // 4 x 4
    const int g = lane >> 2, tq = lane & 3;
    const int m0 = blockIdx.x * 64;
    const uint32_t sbase = smem_u32(lsm);

    // cp.async indices: A 512 chunks (1/thread), B 1024 chunks (2/thread)
    const int arow = tid >> 3;            // 0..63
    const int ac   = tid & 7;             // 16B chunk in 128B row
    const int brow = tid >> 3;            // 0..63
    const int bc   = (tid & 7) * 2;       // chunk pair in 256B row

    float acc[2][4];
    #pragma unroll
    for (int b = 0; b < 2; b++)
        #pragma unroll
        for (int c = 0; c < 4; c++) acc[b][c] = 0.f;

    auto issue = [&](int kt, int s) {
        const uint32_t sA = sbase + s * LG_STAGE;
        const uint32_t sB = sA + LGA_TILE;
        cp16(sA + arow * LGA_STRIDE + ac * 16,
             x + (size_t)(m0 + arow) * D_DIM + kt * 32 + ac * 4);
        const float* srcB = g_Wgs + (size_t)brow * (D_DIM * 2) + kt * 64;
        cp16(sB + brow * LGB_STRIDE + bc * 16,       srcB + bc * 4);
        cp16(sB + brow * LGB_STRIDE + (bc + 1) * 16, srcB + (bc + 1) * 4);
    };

    const int NKT = D_DIM / 32;   // 64
    issue(0, 0); cp_commit();
    issue(1, 1); cp_commit();
    issue(2, 2); cp_commit();

    for (int kt = 0; kt < NKT; kt++) {
        cp_wait2();
        __syncthreads();
        if (kt + 3 < NKT) issue(kt + 3, (kt + 3) & 3);
        cp_commit();

        const int s = kt & 3;
        const uint32_t sA = sbase + s * LG_STAGE;
        const uint32_t sB = sA + LGA_TILE;
        const uint32_t aRow0 = sA + (warp_m * 16 + g) * LGA_STRIDE;
        const uint32_t aRow8 = aRow0 + 8 * LGA_STRIDE;
        const uint32_t bBase = sB + (warp_n * 16 + g) * LGB_STRIDE;

        #pragma unroll
        for (int kk = 0; kk < 4; kk++) {
            const int k0 = kk * 8 + tq;
            float a0 = lds32(aRow0 + k0 * 4);
            float a1 = lds32(aRow8 + k0 * 4);
            float a2 = lds32(aRow0 + (k0 + 4) * 4);
            float a3 = lds32(aRow8 + (k0 + 4) * 4);
            uint2 s0 = tf32split(a0), s1 = tf32split(a1);
            uint2 s2 = tf32split(a2), s3 = tf32split(a3);
            #pragma unroll
            for (int nt = 0; nt < 2; nt++) {
                const uint32_t bb = bBase + nt * 8 * LGB_STRIDE + kk * 64;
                uint2 b0 = lds64(bb + tq * 8);
                uint2 b1 = lds64(bb + (tq + 4) * 8);
                mma1688t(acc[nt], s0.x, s1.x, s2.x, s3.x, b0.x, b1.x);  // hi*hi
                mma1688t(acc[nt], s0.x, s1.x, s2.x, s3.x, b0.y, b1.y);  // hi*lo
                mma1688t(acc[nt], s0.y, s1.y, s2.y, s3.y, b0.x, b1.x);  // lo*hi
            }
        }
    }

    // store logits
    const int m = m0 + warp_m * 16 + g;
    #pragma unroll
    for (int nt = 0; nt < 2; nt++) {
        const int n = warp_n * 16 + nt * 8 + 2 * tq;
        *(float2*)&g_logits[(size_t)m * E_EXP + n] = make_float2(acc[nt][0], acc[nt][1]);
        *(float2*)&g_logits[(size_t)(m + 8) * E_EXP + n] = make_float2(acc[nt][2], acc[nt][3]);
    }
}

// ---------------- h1: HMMA bf16 GEMM, block 128x256, warp tile 64x64 ------
// 256 threads = 8 warps (warp_m = wid&1 over 2x64 rows, warp_n = wid>>1 over
// 4x64 cols). BK=32, 4-stage cp.async depth-3. 64x64 warp tiles double the
// fragment reuse: smem reads drop from 96KB to 64KB per SM-kt, lifting the
// smem-crossbar-bound tensor ceiling from ~57% to ~74%.
#define ROWB 80
#define H2_A_TILE (128 * ROWB)            // 10240
#define H2_B_TILE (256 * ROWB)            // 20480
#define H2_STAGE  (H2_A_TILE + H2_B_TILE) // 30720
#define H2_SMEM   (4 * H2_STAGE)          // 122880

__global__ __launch_bounds__(256, 1)
void k_h1(const float* __restrict__ W2) {
    extern __shared__ __align__(16) char hsm[];
    const int tid = threadIdx.x;
    const int wid = tid >> 5, lane = tid & 31;
    const int warp_m = wid & 1, warp_n = wid >> 1;   // 2 x 4
    const int m0 = blockIdx.y * 128;
    const int n0 = blockIdx.x * 256;
    const uint32_t sbase = smem_u32(hsm);

    const int ldrow = tid >> 2;           // 0..63
    const int ldc4  = tid & 3;            // 16B chunk in 64B row
    const int sub = lane >> 3;
    const int l7  = lane & 7;

    float acc[4][8][4];                   // [mt][2*ng+j][4] = 128 regs
    #pragma unroll
    for (int a = 0; a < 4; a++)
        #pragma unroll
        for (int b = 0; b < 8; b++)
            #pragma unroll
            for (int c = 0; c < 4; c++) acc[a][b][c] = 0.f;

    auto issue = [&](int kt, int s) {
        const uint32_t sA = sbase + s * H2_STAGE;
        const uint32_t sB = sA + H2_A_TILE;
        // A: 128 rows x 4 chunks = 512 cp16 (2/thread)
        #pragma unroll
        for (int i = 0; i < 2; i++) {
            int row = ldrow + i * 64;
            cp16(sA + row * ROWB + ldc4 * 16,
                 g_xb + (size_t)(m0 + row) * D_DIM + kt * 32 + ldc4 * 8);
        }
        // B: 256 rows x 4 chunks = 1024 cp16 (4/thread)
        #pragma unroll
        for (int i = 0; i < 4; i++) {
            int row = ldrow + i * 64;
            cp16(sB + row * ROWB + ldc4 * 16,
                 g_Wb + (size_t)(n0 + row) * D_DIM + kt * 32 + ldc4 * 8);
        }
    };

    const int NKT = D_DIM / 32;   // 64
    issue(0, 0); cp_commit();
    issue(1, 1); cp_commit();
    issue(2, 2); cp_commit();

    for (int kt = 0; kt < NKT; kt++) {
        cp_wait2();
        __syncthreads();
        if (kt + 3 < NKT) issue(kt + 3, (kt + 3) & 3);
        cp_commit();

        const int s = kt & 3;
        const uint32_t sA = sbase + s * H2_STAGE;
        const uint32_t sB = sA + H2_A_TILE;
        #pragma unroll
        for (int ks = 0; ks < 2; ks++) {
            uint32_t afr[4][4];
            #pragma unroll
            for (int mt = 0; mt < 4; mt++) {
                int rowA = warp_m * 64 + mt * 16 + ((sub & 1) << 3) + l7;
                ldm4(afr[mt], sA + rowA * ROWB + ((sub >> 1) << 4) + ks * 32);
            }
            uint32_t bfr[4][4];
            #pragma unroll
            for (int ng = 0; ng < 4; ng++) {
                int rowB = warp_n * 64 + ng * 16 + ((sub >> 1) << 3) + l7;
                ldm4(bfr[ng], sB + rowB * ROWB + ((sub & 1) << 4) + ks * 32);
            }
            #pragma unroll
            for (int mt = 0; mt < 4; mt++)
                #pragma unroll
                for (int ng = 0; ng < 4; ng++) {
                    mma16816(acc[mt][2 * ng + 0], afr[mt], bfr[ng][0], bfr[ng][1]);
                    mma16816(acc[mt][2 * ng + 1], afr[mt], bfr[ng][2], bfr[ng][3]);
                }
        }
    }

    // ---- epilogue: LN-fold + exact GELU + dot W2 -> quad-reduce -> atomic z
    const int groupID = lane >> 2, tig = lane & 3;
    #pragma unroll
    for (int mt = 0; mt < 4; mt++) {
        const int R0 = m0 + warp_m * 64 + mt * 16 + groupID;
        const int R1 = R0 + 8;
        const float mu0 = g_mu[R0], rs0 = g_rs[R0];
        const float mu1 = g_mu[R1], rs1 = g_rs[R1];
        float z0 = 0.f, z1 = 0.f;
        #pragma unroll
        for (int idx = 0; idx < 8; idx++) {
            const int n = n0 + warp_n * 64 + idx * 8 + tig * 2;
            const float s_a = g_s[n],     t_a = g_t[n],     w_a = W2[n];
            const float s_b = g_s[n + 1], t_b = g_t[n + 1], w_b = W2[n + 1];
            float h, g;
            h = rs0 * (acc[mt][idx][0] - mu0 * s_a) + t_a;
            g = 0.5f * h * (1.0f + erff(h * 0.70710678118654752f));
            z0 = fmaf(g, w_a, z0);
            h = rs0 * (acc[mt][idx][1] - mu0 * s_b) + t_b;
            g = 0.5f * h * (1.0f + erff(h * 0.70710678118654752f));
            z0 = fmaf(g, w_b, z0);
            h = rs1 * (acc[mt][idx][2] - mu1 * s_a) + t_a;
            g = 0.5f * h * (1.0f + erff(h * 0.70710678118654752f));
            z1 = fmaf(g, w_a, z1);
            h = rs1 * (acc[mt][idx][3] - mu1 * s_b) + t_b;
            g = 0.5f * h * (1.0f + erff(h * 0.70710678118654752f));
            z1 = fmaf(g, w_b, z1);
        }
        #pragma unroll
        for (int o = 1; o < 4; o <<= 1) {
            z0 += __shfl_xor_sync(0xffffffffu, z0, o);
            z1 += __shfl_xor_sync(0xffffffffu, z1, o);
        }
        if (tig == 0) {
            atomicAdd(&g_z[R0], z0);
            atomicAdd(&g_z[R1], z1);
        }
    }
}

// ---------------- final: sigmoid, modulate, softmax, top-2, outputs -------
__global__ void k_final(float* __restrict__ out) {
    float* o_idx  = out;                       // 16384*2
    float* o_sc   = out + 32768;               // 16384*2
    float* o_pr   = out + 65536;               // 16384*64
    float* o_imp  = out + 65536 + M_TOK * E_EXP;
    float* o_load = o_imp + E_EXP;

    const int warp = threadIdx.x >> 5;
    const int lane = threadIdx.x & 31;
    const int token = blockIdx.x * 8 + warp;

    __shared__ float s_imp[E_EXP];
    __shared__ float s_load[E_EXP];
    if (threadIdx.x < E_EXP) { s_imp[threadIdx.x] = 0.f; s_load[threadIdx.x] = 0.f; }
    __syncthreads();

    const float* lrow = g_logits + (size_t)token * E_EXP;
    float z    = g_z[token];
    float diff = 1.0f / (1.0f + expf(-z));
    float c    = 1.0f / (1.0f + diff);        // TEMP = 1
    float l0 = lrow[lane] * c;
    float l1 = lrow[lane + 32] * c;

    float mx = fmaxf(l0, l1);
    #pragma unroll
    for (int o = 16; o; o >>= 1) mx = fmaxf(mx, __shfl_xor_sync(0xffffffffu, mx, o));
    float p0 = expf(l0 - mx), p1 = expf(l1 - mx);
    float sum = p0 + p1;
    #pragma unroll
    for (int o = 16; o; o >>= 1) sum += __shfl_xor_sync(0xffffffffu, sum, o);
    float inv = 1.0f / sum;
    p0 *= inv; p1 *= inv;
    o_pr[(size_t)token * E_EXP + lane]      = p0;
    o_pr[(size_t)token * E_EXP + lane + 32] = p1;

    float v; int bi;
    if (l1 > l0) { v = l1; bi = lane + 32; } else { v = l0; bi = lane; }
    #pragma unroll
    for (int o = 16; o; o >>= 1) {
        float ov = __shfl_xor_sync(0xffffffffu, v, o);
        int   oi = __shfl_xor_sync(0xffffffffu, bi, o);
        if (ov > v || (ov == v && oi < bi)) { v = ov; bi = oi; }
    }
    const int i1 = bi;

    const float NEGINF = __int_as_float(0xff800000);
    float c0 = (lane == i1)      ? NEGINF : l0;
    float c1 = (lane + 32 == i1) ? NEGINF : l1;
    if (c1 > c0) { v = c1; bi = lane + 32; } else { v = c0; bi = lane; }
    #pragma unroll
    for (int o = 16; o; o >>= 1) {
        float ov = __shfl_xor_sync(0xffffffffu, v, o);
        int   oi = __shfl_xor_sync(0xffffffffu, bi, o);
        if (ov > v || (ov == v && oi < bi)) { v = ov; bi = oi; }
    }
    const int i2 = bi;

    int src1 = i1 & 31;
    float pa = __shfl_sync(0xffffffffu, p0, src1);
    float pb = __shfl_sync(0xffffffffu, p1, src1);
    float pv1 = (i1 < 32) ? pa : pb;
    int src2 = i2 & 31;
    float pc = __shfl_sync(0xffffffffu, p0, src2);
    float pd = __shfl_sync(0xffffffffu, p1, src2);
    float pv2 = (i2 < 32) ? pc : pd;
    if (lane == 0) {
        float s1 = (1.0f - pv1) + pv1;
        float s2 = (1.0f - pv2) + pv2;
        float den = fmaxf(s1 + s2, 1e-9f);
        o_idx[token * 2 + 0] = (float)i1;
        o_idx[token * 2 + 1] = (float)i2;
        o_sc[token * 2 + 0]  = s1 / den;
        o_sc[token * 2 + 1]  = s2 / den;
    }

    atomicAdd(&s_imp[lane], p0);
    atomicAdd(&s_imp[lane + 32], p1);
    if (lane == 0) { atomicAdd(&s_load[i1], 1.0f); atomicAdd(&s_load[i2], 1.0f); }
    __syncthreads();
    if (threadIdx.x < E_EXP) {
        atomicAdd(&o_imp[threadIdx.x],  s_imp[threadIdx.x]  * (1.0f / (float)M_TOK));
        atomicAdd(&o_load[threadIdx.x], s_load[threadIdx.x] * (1.0f / (float)M_TOK));
    }
}

// ---------------- launch ---------------------------------------------------
// k_h1 (default stream) and k_logits (side stream) fork-join; with h1 now at
// 1 block/SM (122KB smem) co-residency is still blocked, but the tail drain
// overlaps. k_h1 stays the profiled 4th launch.
extern "C" void kernel_launch(void* const* d_in, const int* in_sizes, int n_in,
                              void* d_out, int out_size) {
    const float* x     = (const float*)d_in[0];
    const float* Wg    = (const float*)d_in[1];
    const float* gamma = (const float*)d_in[2];
    const float* beta  = (const float*)d_in[3];
    const float* W1    = (const float*)d_in[4];
    const float* W2    = (const float*)d_in[5];
    float* out = (float*)d_out;

    static int init_done = 0;
    static cudaStream_t s_side;
    static cudaEvent_t  s_fork, s_join;
    if (!init_done) {
        cudaFuncSetAttribute(k_logits, cudaFuncAttributeMaxDynamicSharedMemorySize, LG_SMEM);
        cudaFuncSetAttribute(k_h1,     cudaFuncAttributeMaxDynamicSharedMemorySize, H2_SMEM);
        cudaStreamCreateWithFlags(&s_side, cudaStreamNonBlocking);
        cudaEventCreateWithFlags(&s_fork, cudaEventDisableTiming);
        cudaEventCreateWithFlags(&s_join, cudaEventDisableTiming);
        init_done = 1;
    }

    k_init<<<(M_TOK + 255) / 256, 256>>>(out + 65536 + (size_t)M_TOK * E_EXP);
    k_stats_cvt<<<M_TOK, 256>>>(x);
    k_prep<<<H_DIM + E_EXP, 256>>>(gamma, beta, W1, Wg);

    cudaEventRecord(s_fork, 0);
    cudaStreamWaitEvent(s_side, s_fork, 0);
    k_h1<<<dim3(H_DIM / 256, M_TOK / 128), 256, H2_SMEM>>>(W2);
    k_logits<<<M_TOK / 64, 512, LG_SMEM, s_side>>>(x);
    cudaEventRecord(s_join, s_side);
    cudaStreamWaitEvent(0, s_join, 0);

    k_final<<<M_TOK / 8, 256>>>(out);
}

// round 14
// speedup vs baseline: 1.9392x; 1.9392x over previous
#include <cuda_runtime.h>
#include <cuda_bf16.h>
#include <math.h>
#include <stdint.h>

#define M_TOK 16384
#define D_DIM 2048
#define E_EXP 64
#define H_DIM 1024

// ---- scratch (static __device__ arrays: allocation-free) ----
__device__ float g_mu[M_TOK];
__device__ float g_rs[M_TOK];
__device__ float g_z[M_TOK];
__device__ float g_logits[M_TOK * E_EXP];                 // 4 MB
__device__ __nv_bfloat16 g_xb[(size_t)M_TOK * D_DIM];     // 64 MB
__device__ __nv_bfloat16 g_Wb[(size_t)H_DIM * D_DIM];     // 4 MB (gamma*W1 bf16)
__device__ float g_Wgs[(size_t)E_EXP * D_DIM * 2];        // 1 MB tf32 (hi,lo) pairs of Wg
__device__ float g_s[H_DIM];
__device__ float g_t[H_DIM];

// =================== PTX helpers (family-generic only) ===================
__device__ __forceinline__ uint32_t smem_u32(const void* p) {
    return (uint32_t)__cvta_generic_to_shared(p);
}
__device__ __forceinline__ void cp16(uint32_t dst, const void* src) {
    asm volatile("cp.async.cg.shared.global [%0], [%1], 16;" :: "r"(dst), "l"(src));
}
__device__ __forceinline__ void cp_commit() { asm volatile("cp.async.commit_group;"); }
__device__ __forceinline__ void cp_wait2()  { asm volatile("cp.async.wait_group 2;"); }
__device__ __forceinline__ void ldm4(uint32_t* r, uint32_t addr) {
    asm volatile("ldmatrix.sync.aligned.m8n8.x4.shared.b16 {%0,%1,%2,%3}, [%4];"
                 : "=r"(r[0]), "=r"(r[1]), "=r"(r[2]), "=r"(r[3]) : "r"(addr));
}
__device__ __forceinline__ void mma16816(float* c, const uint32_t* a, uint32_t b0, uint32_t b1) {
    asm volatile("mma.sync.aligned.m16n8k16.row.col.f32.bf16.bf16.f32 "
                 "{%0,%1,%2,%3}, {%4,%5,%6,%7}, {%8,%9}, {%0,%1,%2,%3};"
                 : "+f"(c[0]), "+f"(c[1]), "+f"(c[2]), "+f"(c[3])
                 : "r"(a[0]), "r"(a[1]), "r"(a[2]), "r"(a[3]), "r"(b0), "r"(b1));
}
__device__ __forceinline__ void mma1688t(float* c, uint32_t a0, uint32_t a1, uint32_t a2,
                                         uint32_t a3, uint32_t b0, uint32_t b1) {
    asm volatile("mma.sync.aligned.m16n8k8.row.col.f32.tf32.tf32.f32 "
                 "{%0,%1,%2,%3}, {%4,%5,%6,%7}, {%8,%9}, {%0,%1,%2,%3};"
                 : "+f"(c[0]), "+f"(c[1]), "+f"(c[2]), "+f"(c[3])
                 : "r"(a0), "r"(a1), "r"(a2), "r"(a3), "r"(b0), "r"(b1));
}
__device__ __forceinline__ uint2 lds64(uint32_t a) {
    uint2 r;
    asm volatile("ld.shared.v2.b32 {%0,%1}, [%2];" : "=r"(r.x), "=r"(r.y) : "r"(a));
    return r;
}
__device__ __forceinline__ float lds32(uint32_t a) {
    float r;
    asm volatile("ld.shared.b32 %0, [%1];" : "=f"(r) : "r"(a));
    return r;
}
// 3xTF32 split: BOTH halves go through cvt.rna.tf32 so the MMA input
// registers hold exact tf32 values (the tensor core adds no further error).
// R9 lesson: a bit-masked hi + raw-fp32 lo gets truncated inside the MMA and
// the biased residuals flipped top-k indices (rel_err 2.3e-3). Do not
// "optimize" this back to a mask split.
__device__ __forceinline__ uint2 tf32split(float v) {
    uint32_t hi, lo;
    asm("cvt.rna.tf32.f32 %0, %1;" : "=r"(hi) : "f"(v));
    float r = v - __uint_as_float(hi);
    asm("cvt.rna.tf32.f32 %0, %1;" : "=r"(lo) : "f"(r));
    return make_uint2(hi, lo);
}

// ---------------- per-token LN stats + bf16 convert (x read once) ---------
__global__ void k_stats_cvt(const float* __restrict__ x) {
    int t = blockIdx.x;
    const float4* xr = (const float4*)(x + (size_t)t * D_DIM);
    __nv_bfloat162* xb = (__nv_bfloat162*)(g_xb + (size_t)t * D_DIM);
    float s = 0.f, ss = 0.f;
    for (int i = threadIdx.x; i < D_DIM / 4; i += blockDim.x) {
        float4 v = xr[i];
        s  += v.x + v.y + v.z + v.w;
        ss += v.x * v.x + v.y * v.y + v.z * v.z + v.w * v.w;
        xb[2 * i + 0] = __floats2bfloat162_rn(v.x, v.y);
        xb[2 * i + 1] = __floats2bfloat162_rn(v.z, v.w);
    }
    #pragma unroll
    for (int o = 16; o; o >>= 1) {
        s  += __shfl_xor_sync(0xffffffffu, s,  o);
        ss += __shfl_xor_sync(0xffffffffu, ss, o);
    }
    __shared__ float red[2][8];
    int w = threadIdx.x >> 5;
    if ((threadIdx.x & 31) == 0) { red[0][w] = s; red[1][w] = ss; }
    __syncthreads();
    if (threadIdx.x == 0) {
        float S = 0.f, SS = 0.f;
        for (int i = 0; i < (int)(blockDim.x >> 5); i++) { S += red[0][i]; SS += red[1][i]; }
        float mu  = S / (float)D_DIM;
        float var = SS / (float)D_DIM - mu * mu;
        g_mu[t] = mu;
        g_rs[t] = rsqrtf(var + 1e-5f);
    }
}

// ---------------- prep: Wb=bf16(gamma*W1), s_j,t_j; Wg tf32 split; zeroing -
__global__ void k_prep(const float* __restrict__ gamma, const float* __restrict__ beta,
                       const float* __restrict__ W1, const float* __restrict__ Wg,
                       float* __restrict__ d_impload) {
    int n = blockIdx.x;
    if (n >= H_DIM + E_EXP) {
        // init branch: zero g_z and the importance/load tail of d_out
        int idx = (n - H_DIM - E_EXP) * 256 + threadIdx.x;
        if (idx < M_TOK) g_z[idx] = 0.0f;
        if (idx < 128)   d_impload[idx] = 0.0f;
        return;
    }
    if (n >= H_DIM) {
        int e = n - H_DIM;
        const float* src = Wg + (size_t)e * D_DIM;
        float2* dst = (float2*)(g_Wgs + (size_t)e * D_DIM * 2);
        for (int i = threadIdx.x; i < D_DIM; i += blockDim.x) {
            uint2 p = tf32split(src[i]);
            dst[i] = make_float2(__uint_as_float(p.x), __uint_as_float(p.y));
        }
        return;
    }
    int j = n;
    const float* w1r = W1 + (size_t)j * D_DIM;
    __nv_bfloat16* dst = g_Wb + (size_t)j * D_DIM;
    float sj = 0.f, tj = 0.f;
    for (int i = threadIdx.x; i < D_DIM; i += blockDim.x) {
        float g = gamma[i], w = w1r[i];
        float gw = g * w;
        dst[i] = __float2bfloat16_rn(gw);
        sj += gw;
        tj += beta[i] * w;
    }
    #pragma unroll
    for (int o = 16; o; o >>= 1) {
        sj += __shfl_xor_sync(0xffffffffu, sj, o);
        tj += __shfl_xor_sync(0xffffffffu, tj, o);
    }
    __shared__ float red[2][8];
    int w = threadIdx.x >> 5;
    if ((threadIdx.x & 31) == 0) { red[0][w] = sj; red[1][w] = tj; }
    __syncthreads();
    if (threadIdx.x == 0) {
        float S = 0.f, T = 0.f;
        for (int i = 0; i < (int)(blockDim.x >> 5); i++) { S += red[0][i]; T += red[1][i]; }
        g_s[j] = S; g_t[j] = T;
    }
}

// ---------------- logits: 3xTF32 tensor GEMM, BM=64 x N=64, BK=32 ---------
// 512 threads = 16 warps: warp_m = wid&3 (16 rows), warp_n = wid>>2 (16 cols).
// 4-stage cp.async, depth-3 prefetch. A raw fp32 (stride 144B), cvt.rna
// tf32-split at fragment load. B pre-split (hi,lo) pairs (stride 288B).
#define LGA_STRIDE 144
#define LGB_STRIDE 288
#define LGA_TILE (64 * LGA_STRIDE)            // 9216
#define LGB_TILE (64 * LGB_STRIDE)            // 18432
#define LG_STAGE (LGA_TILE + LGB_TILE)        // 27648
#define LG_SMEM  (4 * LG_STAGE)               // 110592

__global__ __launch_bounds__(512, 2)
void k_logits(const float* __restrict__ x) {
    extern __shared__ __align__(16) char lsm[];
    const int tid = threadIdx.x;
    const int wid = tid >> 5, lane = tid & 31;
    const int warp_m = wid & 3, warp_n = wid >> 2;    // 4 x 4
    const int g = lane >> 2, tq = lane & 3;
    const int m0 = blockIdx.x * 64;
    const uint32_t sbase = smem_u32(lsm);

    const int arow = tid >> 3;            // 0..63
    const int ac   = tid & 7;             // 16B chunk in 128B row
    const int brow = tid >> 3;            // 0..63
    const int bc   = (tid & 7) * 2;       // chunk pair in 256B row

    float acc[2][4];
    #pragma unroll
    for (int b = 0; b < 2; b++)
        #pragma unroll
        for (int c = 0; c < 4; c++) acc[b][c] = 0.f;

    auto issue = [&](int kt, int s) {
        const uint32_t sA = sbase + s * LG_STAGE;
        const uint32_t sB = sA + LGA_TILE;
        cp16(sA + arow * LGA_STRIDE + ac * 16,
             x + (size_t)(m0 + arow) * D_DIM + kt * 32 + ac * 4);
        const float* srcB = g_Wgs + (size_t)brow * (D_DIM * 2) + kt * 64;
        cp16(sB + brow * LGB_STRIDE + bc * 16,       srcB + bc * 4);
        cp16(sB + brow * LGB_STRIDE + (bc + 1) * 16, srcB + (bc + 1) * 4);
    };

    const int NKT = D_DIM / 32;   // 64
    issue(0, 0); cp_commit();
    issue(1, 1); cp_commit();
    issue(2, 2); cp_commit();

    for (int kt = 0; kt < NKT; kt++) {
        cp_wait2();
        __syncthreads();
        if (kt + 3 < NKT) issue(kt + 3, (kt + 3) & 3);
        cp_commit();

        const int s = kt & 3;
        const uint32_t sA = sbase + s * LG_STAGE;
        const uint32_t sB = sA + LGA_TILE;
        const uint32_t aRow0 = sA + (warp_m * 16 + g) * LGA_STRIDE;
        const uint32_t aRow8 = aRow0 + 8 * LGA_STRIDE;
        const uint32_t bBase = sB + (warp_n * 16 + g) * LGB_STRIDE;

        #pragma unroll
        for (int kk = 0; kk < 4; kk++) {
            const int k0 = kk * 8 + tq;
            float a0 = lds32(aRow0 + k0 * 4);
            float a1 = lds32(aRow8 + k0 * 4);
            float a2 = lds32(aRow0 + (k0 + 4) * 4);
            float a3 = lds32(aRow8 + (k0 + 4) * 4);
            uint2 s0 = tf32split(a0), s1 = tf32split(a1);
            uint2 s2 = tf32split(a2), s3 = tf32split(a3);
            #pragma unroll
            for (int nt = 0; nt < 2; nt++) {
                const uint32_t bb = bBase + nt * 8 * LGB_STRIDE + kk * 64;
                uint2 b0 = lds64(bb + tq * 8);
                uint2 b1 = lds64(bb + (tq + 4) * 8);
                mma1688t(acc[nt], s0.x, s1.x, s2.x, s3.x, b0.x, b1.x);  // hi*hi
                mma1688t(acc[nt], s0.x, s1.x, s2.x, s3.x, b0.y, b1.y);  // hi*lo
                mma1688t(acc[nt], s0.y, s1.y, s2.y, s3.y, b0.x, b1.x);  // lo*hi
            }
        }
    }

    const int m = m0 + warp_m * 16 + g;
    #pragma unroll
    for (int nt = 0; nt < 2; nt++) {
        const int n = warp_n * 16 + nt * 8 + 2 * tq;
        *(float2*)&g_logits[(size_t)m * E_EXP + n] = make_float2(acc[nt][0], acc[nt][1]);
        *(float2*)&g_logits[(size_t)(m + 8) * E_EXP + n] = make_float2(acc[nt][2], acc[nt][3]);
    }
}

// ---------------- h1: HMMA bf16 GEMM 128x128, BK=32, 4-stage cp.async -----
// (R10/R11 proven config: 8 warps of 32x64 tiles, 2 blocks/SM, 213-215us)
#define ROWB 80
#define H1_TILE (128 * ROWB)          // 10240 per operand per stage
#define H1_STAGE (2 * H1_TILE)        // 20480
#define H1_SMEM (4 * H1_STAGE)        // 81920

__global__ __launch_bounds__(256, 2)
void k_h1(const float* __restrict__ W2) {
    extern __shared__ __align__(16) char hsm[];
    const int tid = threadIdx.x;
    const int wid = tid >> 5, lane = tid & 31;
    const int warp_m = wid & 3, warp_n = wid >> 2;
    const int m0 = blockIdx.y * 128;
    const int n0 = blockIdx.x * 128;
    const uint32_t sbase = smem_u32(hsm);

    const int ldrow0 = tid >> 2;          // 0..63
    const int ldc4   = tid & 3;           // 16B chunk in row
    const int sub = lane >> 3;
    const int l7  = lane & 7;

    float acc[2][8][4];
    #pragma unroll
    for (int a = 0; a < 2; a++)
        #pragma unroll
        for (int b = 0; b < 8; b++)
            #pragma unroll
            for (int c = 0; c < 4; c++) acc[a][b][c] = 0.f;

    auto issue = [&](int kt, int s) {
        const uint32_t sA = sbase + s * H1_STAGE;
        const uint32_t sB = sA + H1_TILE;
        #pragma unroll
        for (int i = 0; i < 2; i++) {
            int row = ldrow0 + i * 64;
            cp16(sA + row * ROWB + ldc4 * 16,
                 g_xb + (size_t)(m0 + row) * D_DIM + kt * 32 + ldc4 * 8);
            cp16(sB + row * ROWB + ldc4 * 16,
                 g_Wb + (size_t)(n0 + row) * D_DIM + kt * 32 + ldc4 * 8);
        }
    };

    const int NKT = D_DIM / 32;   // 64
    issue(0, 0); cp_commit();
    issue(1, 1); cp_commit();
    issue(2, 2); cp_commit();

    for (int kt = 0; kt < NKT; kt++) {
        cp_wait2();
        __syncthreads();
        if (kt + 3 < NKT) issue(kt + 3, (kt + 3) & 3);
        cp_commit();

        const int s = kt & 3;
        const uint32_t sA = sbase + s * H1_STAGE;
        const uint32_t sB = sA + H1_TILE;
        #pragma unroll
        for (int ks = 0; ks < 2; ks++) {
            uint32_t afr[2][4];
            #pragma unroll
            for (int mt = 0; mt < 2; mt++) {
                int rowA = warp_m * 32 + mt * 16 + ((sub & 1) << 3) + l7;
                ldm4(afr[mt], sA + rowA * ROWB + ((sub >> 1) << 4) + ks * 32);
            }
            uint32_t bfr[4][4];
            #pragma unroll
            for (int g4 = 0; g4 < 4; g4++) {
                int rowB = warp_n * 64 + g4 * 16 + ((sub >> 1) << 3) + l7;
                ldm4(bfr[g4], sB + rowB * ROWB + ((sub & 1) << 4) + ks * 32);
            }
            #pragma unroll
            for (int mt = 0; mt < 2; mt++)
                #pragma unroll
                for (int g4 = 0; g4 < 4; g4++) {
                    mma16816(acc[mt][2 * g4 + 0], afr[mt], bfr[g4][0], bfr[g4][1]);
                    mma16816(acc[mt][2 * g4 + 1], afr[mt], bfr[g4][2], bfr[g4][3]);
                }
        }
    }

    // ---- epilogue: LN-fold + exact GELU + dot W2 -> quad-reduce -> atomic z
    const int groupID = lane >> 2, tig = lane & 3;
    #pragma unroll
    for (int mt = 0; mt < 2; mt++) {
        const int R0 = m0 + warp_m * 32 + mt * 16 + groupID;
        const int R1 = R0 + 8;
        const float mu0 = g_mu[R0], rs0 = g_rs[R0];
        const float mu1 = g_mu[R1], rs1 = g_rs[R1];
        float z0 = 0.f, z1 = 0.f;
        #pragma unroll
        for (int nt = 0; nt < 8; nt++) {
            const int n = n0 + warp_n * 64 + nt * 8 + tig * 2;
            const float s_a = g_s[n],     t_a = g_t[n],     w_a = W2[n];
            const float s_b = g_s[n + 1], t_b = g_t[n + 1], w_b = W2[n + 1];
            float h, g;
            h = rs0 * (acc[mt][nt][0] - mu0 * s_a) + t_a;
            g = 0.5f * h * (1.0f + erff(h * 0.70710678118654752f));
            z0 = fmaf(g, w_a, z0);
            h = rs0 * (acc[mt][nt][1] - mu0 * s_b) + t_b;
            g = 0.5f * h * (1.0f + erff(h * 0.70710678118654752f));
            z0 = fmaf(g, w_b, z0);
            h = rs1 * (acc[mt][nt][2] - mu1 * s_a) + t_a;
            g = 0.5f * h * (1.0f + erff(h * 0.70710678118654752f));
            z1 = fmaf(g, w_a, z1);
            h = rs1 * (acc[mt][nt][3] - mu1 * s_b) + t_b;
            g = 0.5f * h * (1.0f + erff(h * 0.70710678118654752f));
            z1 = fmaf(g, w_b, z1);
        }
        #pragma unroll
        for (int o = 1; o < 4; o <<= 1) {
            z0 += __shfl_xor_sync(0xffffffffu, z0, o);
            z1 += __shfl_xor_sync(0xffffffffu, z1, o);
        }
        if (tig == 0) {
            atomicAdd(&g_z[R0], z0);
            atomicAdd(&g_z[R1], z1);
        }
    }
}

// ---------------- final: sigmoid, modulate, softmax, top-2, outputs -------
__global__ void k_final(float* __restrict__ out) {
    float* o_idx  = out;                       // 16384*2
    float* o_sc   = out + 32768;               // 16384*2
    float* o_pr   = out + 65536;               // 16384*64
    float* o_imp  = out + 65536 + M_TOK * E_EXP;
    float* o_load = o_imp + E_EXP;

    const int warp = threadIdx.x >> 5;
    const int lane = threadIdx.x & 31;
    const int token = blockIdx.x * 8 + warp;

    __shared__ float s_imp[E_EXP];
    __shared__ float s_load[E_EXP];
    if (threadIdx.x < E_EXP) { s_imp[threadIdx.x] = 0.f; s_load[threadIdx.x] = 0.f; }
    __syncthreads();

    const float* lrow = g_logits + (size_t)token * E_EXP;
    float z    = g_z[token];
    float diff = 1.0f / (1.0f + expf(-z));
    float c    = 1.0f / (1.0f + diff);        // TEMP = 1
    float l0 = lrow[lane] * c;
    float l1 = lrow[lane + 32] * c;

    float mx = fmaxf(l0, l1);
    #pragma unroll
    for (int o = 16; o; o >>= 1) mx = fmaxf(mx, __shfl_xor_sync(0xffffffffu, mx, o));
    float p0 = expf(l0 - mx), p1 = expf(l1 - mx);
    float sum = p0 + p1;
    #pragma unroll
    for (int o = 16; o; o >>= 1) sum += __shfl_xor_sync(0xffffffffu, sum, o);
    float inv = 1.0f / sum;
    p0 *= inv; p1 *= inv;
    o_pr[(size_t)token * E_EXP + lane]      = p0;
    o_pr[(size_t)token * E_EXP + lane + 32] = p1;

    float v; int bi;
    if (l1 > l0) { v = l1; bi = lane + 32; } else { v = l0; bi = lane; }
    #pragma unroll
    for (int o = 16; o; o >>= 1) {
        float ov = __shfl_xor_sync(0xffffffffu, v, o);
        int   oi = __shfl_xor_sync(0xffffffffu, bi, o);
        if (ov > v || (ov == v && oi < bi)) { v = ov; bi = oi; }
    }
    const int i1 = bi;

    const float NEGINF = __int_as_float(0xff800000);
    float c0 = (lane == i1)      ? NEGINF : l0;
    float c1 = (lane + 32 == i1) ? NEGINF : l1;
    if (c1 > c0) { v = c1; bi = lane + 32; } else { v = c0; bi = lane; }
    #pragma unroll
    for (int o = 16; o; o >>= 1) {
        float ov = __shfl_xor_sync(0xffffffffu, v, o);
        int   oi = __shfl_xor_sync(0xffffffffu, bi, o);
        if (ov > v || (ov == v && oi < bi)) { v = ov; bi = oi; }
    }
    const int i2 = bi;

    int src1 = i1 & 31;
    float pa = __shfl_sync(0xffffffffu, p0, src1);
    float pb = __shfl_sync(0xffffffffu, p1, src1);
    float pv1 = (i1 < 32) ? pa : pb;
    int src2 = i2 & 31;
    float pc = __shfl_sync(0xffffffffu, p0, src2);
    float pd = __shfl_sync(0xffffffffu, p1, src2);
    float pv2 = (i2 < 32) ? pc : pd;
    if (lane == 0) {
        float s1 = (1.0f - pv1) + pv1;
        float s2 = (1.0f - pv2) + pv2;
        float den = fmaxf(s1 + s2, 1e-9f);
        o_idx[token * 2 + 0] = (float)i1;
        o_idx[token * 2 + 1] = (float)i2;
        o_sc[token * 2 + 0]  = s1 / den;
        o_sc[token * 2 + 1]  = s2 / den;
    }

    atomicAdd(&s_imp[lane], p0);
    atomicAdd(&s_imp[lane + 32], p1);
    if (lane == 0) { atomicAdd(&s_load[i1], 1.0f); atomicAdd(&s_load[i2], 1.0f); }
    __syncthreads();
    if (threadIdx.x < E_EXP) {
        atomicAdd(&o_imp[threadIdx.x],  s_imp[threadIdx.x]  * (1.0f / (float)M_TOK));
        atomicAdd(&o_load[threadIdx.x], s_load[threadIdx.x] * (1.0f / (float)M_TOK));
    }
}

// ---------------- launch ---------------------------------------------------
// Reordered for overlap: prep first, then k_logits forks onto the side stream
// EARLY (it only needs x + g_Wgs), overlapping k_stats_cvt and k_h1's ramp on
// the main stream. Launch order keeps k_h1 as the profiled 4th launch:
// prep(1), logits(2), stats(3), h1(4), final(5).
extern "C" void kernel_launch(void* const* d_in, const int* in_sizes, int n_in,
                              void* d_out, int out_size) {
    const float* x     = (const float*)d_in[0];
    const float* Wg    = (const float*)d_in[1];
    const float* gamma = (const float*)d_in[2];
    const float* beta  = (const float*)d_in[3];
    const float* W1    = (const float*)d_in[4];
    const float* W2    = (const float*)d_in[5];
    float* out = (float*)d_out;

    static int init_done = 0;
    static cudaStream_t s_side;
    static cudaEvent_t  s_fork, s_join;
    if (!init_done) {
        cudaFuncSetAttribute(k_logits, cudaFuncAttributeMaxDynamicSharedMemorySize, LG_SMEM);
        cudaFuncSetAttribute(k_h1,     cudaFuncAttributeMaxDynamicSharedMemorySize, H1_SMEM);
        cudaStreamCreateWithFlags(&s_side, cudaStreamNonBlocking);
        cudaEventCreateWithFlags(&s_fork, cudaEventDisableTiming);
        cudaEventCreateWithFlags(&s_join, cudaEventDisableTiming);
        init_done = 1;
    }

    // prep (+ merged init): produces g_Wb/g_s/g_t, g_Wgs, zeros g_z + imp/load
    k_prep<<<H_DIM + E_EXP + 64, 256>>>(gamma, beta, W1, Wg,
                                        out + 65536 + (size_t)M_TOK * E_EXP);

    // fork: logits starts immediately on the side stream
    cudaEventRecord(s_fork, 0);
    cudaStreamWaitEvent(s_side, s_fork, 0);
    k_logits<<<M_TOK / 64, 512, LG_SMEM, s_side>>>(x);

    // main stream: stats then h1 (h1 = 4th launch, profiled)
    k_stats_cvt<<<M_TOK, 256>>>(x);
    k_h1<<<dim3(H_DIM / 128, M_TOK / 128), 256, H1_SMEM>>>(W2);

    cudaEventRecord(s_join, s_side);
    cudaStreamWaitEvent(0, s_join, 0);
    k_final<<<M_TOK / 8, 256>>>(out);
}